// round 14
// baseline (speedup 1.0000x reference)
#include <cuda_runtime.h>
#include <math.h>
#include <stdint.h>

#define TWO_PI_F 6.2831853071795864769f

// ---------------- scratch ----------------
__device__ float g_nodes[4096 * 8];
__device__ float g_label[4096];
__device__ int   g_slot[4096 * 4];
// per-launch precompute
__device__ float g_T[360];
__device__ float g_Wc[2160];
__device__ float g_c2[40];
__device__ float g_extk[6];
__device__ unsigned int g_w2p[9072];       // conv2 weights, bf16 fragment-packed
__device__ uint2 g_wfP[5760];              // dense1 weights k0..k3, bf16x2 pairs
__device__ unsigned int g_wfQ[5760];       // dense1 weights k4..k5, bf16x2

__device__ __forceinline__ float frelu(float x) { return x > 0.f ? x : 0.f; }
__device__ __forceinline__ float dround(float x) {
    return x - sinf(x * TWO_PI_F) / TWO_PI_F;
}
__device__ __forceinline__ uint32_t pack_bf16x2(float lo, float hi) {
    uint32_t v; asm("cvt.rn.bf16x2.f32 %0, %1, %2;" : "=r"(v) : "f"(hi), "f"(lo)); return v;
}
__device__ __forceinline__ uint32_t smem_u32(const void* p) {
    uint32_t a;
    asm("{ .reg .u64 t; cvta.to.shared.u64 t, %1; cvt.u32.u64 %0, t; }" : "=r"(a) : "l"(p));
    return a;
}
__device__ __forceinline__ void cp_async16(uint32_t dst, const void* src) {
    asm volatile("cp.async.cg.shared.global [%0], [%1], 16;" :: "r"(dst), "l"(src));
}
#define CP_COMMIT() asm volatile("cp.async.commit_group;")
#define CP_WAIT(n)  asm volatile("cp.async.wait_group %0;" :: "n"(n))

// ---------------- kernel A1: fully parallel precompute ----------------
__global__ void __launch_bounds__(128) pre_a(
    const float* __restrict__ b1, const float* __restrict__ w2,
    const float* __restrict__ d1w, const int* __restrict__ rcv, int E)
{
    const int t = threadIdx.x;
    const int b = blockIdx.x;
    if (b < 3) {
        int item = b * 128 + t;
        if (item < 360) {
            int tap = item / 40, co = item - 40 * tap;
            float s = 0.f;
            #pragma unroll 8
            for (int ci = 0; ci < 40; ci++)
                s = fmaf(frelu(b1[ci]), __ldg(w2 + tap * 1600 + ci * 40 + co), s);
            g_T[item] = s;
        }
        return;
    }
    if (b < 20) {
        int idx = (b - 3) * 128 + t;
        if (idx < 2160) {
            int cls = idx / 240;
            int rem = idx - 240 * cls;
            int co = rem / 6, k = rem - 6 * co;
            int yc = cls / 3, xc = cls - 3 * yc;
            float s = 0.f;
            for (int p = 0; p < 256; ++p) {
                int y = p >> 4, x = p & 15;
                if (y >= 2 && y <= 13 && x >= 2 && x <= 13) continue;
                int pyc = (y == 0) ? 0 : (y == 15 ? 2 : 1);
                int pxc = (x == 0) ? 0 : (x == 15 ? 2 : 1);
                if (pyc == yc && pxc == xc)
                    s += __ldg(d1w + (p * 40 + co) * 6 + k);
            }
            g_Wc[idx] = s;
        }
        return;
    }
    if (b < 91) {
        int idx = (b - 20) * 128 + t;
        if (idx < 9072) {
            int blk = idx / 84, r = idx - 84 * blk;
            uint32_t v = 0;
            if (r < 80) {
                int n = r >> 1, h = r & 1;
                int tg = blk & 3, sb = blk >> 2;
                int s = sb % 3, tap = sb / 3;
                int ci0 = 16 * s + 2 * tg + 8 * h;
                float lo = (ci0 < 40)     ? __ldg(w2 + tap * 1600 + ci0 * 40 + n)       : 0.f;
                float hi = (ci0 + 1 < 40) ? __ldg(w2 + tap * 1600 + (ci0 + 1) * 40 + n) : 0.f;
                v = pack_bf16x2(lo, hi);
            }
            g_w2p[idx] = v;
        }
        return;
    }
    if (b < 136) {
        int idx = (b - 91) * 128 + t;
        if (idx < 5760) {
            int l = idx & 31, e = (idx >> 5) & 3, T = idx >> 7;
            int MT = T / 5, nt = T - 5 * MT;
            int g2v = l >> 2, tgv = l & 3;
            int p = 16 * MT + g2v + ((e >= 2) ? 8 : 0);
            int co = 8 * nt + 2 * tgv + (e & 1);
            int oy = 2 + p / 12, ox = 2 + p % 12;
            const float* wr = d1w + ((oy * 16 + ox) * 40 + co) * 6;
            g_wfP[idx] = make_uint2(pack_bf16x2(wr[0], wr[1]), pack_bf16x2(wr[2], wr[3]));
            g_wfQ[idx] = pack_bf16x2(wr[4], wr[5]);
        }
        return;
    }
    int e = (b - 136) * 128 + t;
    if (e < E) {
        int r = rcv[e];
        g_slot[r * 4 + ((e / 4032) & 3)] = e + 1;
    }
}

// ---------------- kernel A2: tiny dependent stage ----------------
__global__ void __launch_bounds__(128) pre_b(const float* __restrict__ b2)
{
    const int t = threadIdx.x;
    __shared__ float E[360];
    __shared__ float P[8][6];
    if (t < 40) {
        float s = __ldg(b2 + t);
        #pragma unroll
        for (int tap = 0; tap < 9; tap++) s += g_T[tap * 40 + t];
        g_c2[t] = s;
    }
    for (int item = t; item < 360; item += 128) {
        int cls = item / 40, co = item - 40 * cls;
        int yc = cls / 3, xc = cls - 3 * yc;
        float s = __ldg(b2 + co);
        #pragma unroll
        for (int tap = 0; tap < 9; tap++) {
            int dy = tap / 3, dx = tap % 3;
            bool vy = !((yc == 0 && dy == 0) || (yc == 2 && dy == 2));
            bool vx = !((xc == 0 && dx == 0) || (xc == 2 && dx == 2));
            if (vy && vx) s += g_T[tap * 40 + co];
        }
        E[item] = frelu(s);
    }
    __syncthreads();
    if (t < 48) {
        int k = t % 6, c = t / 6;
        float acc = 0.f;
        #pragma unroll 5
        for (int m = 0; m < 45; ++m) {
            int item = c * 45 + m;
            acc = fmaf(E[item], g_Wc[item * 6 + k], acc);
        }
        P[c][k] = acc;
    }
    __syncthreads();
    if (t < 6) {
        float s = 0.f;
        #pragma unroll
        for (int c = 0; c < 8; c++) s += P[c][t];
        g_extk[t] = s;
    }
}

// ---------------- kernel 1: 128 threads / 2 patches, shared B fragments ----------------
#define K1_SMEM_FLOATS 17648

#define MMA_TILE(Ap, CB, NTLO, NTHI) do {                                     \
    uint32_t a0 = __float_as_uint((Ap)[tg152]);                               \
    uint32_t a1 = __float_as_uint((Ap)[tg152 + 8]);                           \
    uint32_t a2 = __float_as_uint((Ap)[tg152 + 608]);                         \
    uint32_t a3 = __float_as_uint((Ap)[tg152 + 616]);                         \
    _Pragma("unroll")                                                         \
    for (int nt = (NTLO); nt < (NTHI); ++nt) {                                \
        float* c = C[(CB) + nt - (NTLO)];                                     \
        asm("mma.sync.aligned.m16n8k16.row.col.f32.bf16.bf16.f32 "            \
            "{%0,%1,%2,%3}, {%4,%5,%6,%7}, {%8,%9}, {%0,%1,%2,%3};"           \
            : "+f"(c[0]), "+f"(c[1]), "+f"(c[2]), "+f"(c[3])                  \
            : "r"(a0), "r"(a1), "r"(a2), "r"(a3), "r"(B0[nt]), "r"(B1[nt]));  \
    }                                                                         \
} while (0)

// one B load serves BOTH patches' tiles
#define KSTEPS2(MT0, L0, H0, C0, MT1, L1, H1, C1, MT2, L2, H2, C2) do {       \
    _Pragma("unroll")                                                         \
    for (int s = 0; s < 3; ++s) {                                             \
        const float* wk = wb + s * 336 + tg * 84 + 2 * g2;                    \
        uint32_t B0[5], B1[5];                                                \
        _Pragma("unroll")                                                     \
        for (int nt = 0; nt < 5; ++nt) {                                      \
            unsigned long long wv = *(const unsigned long long*)(wk + 16 * nt); \
            B0[nt] = (uint32_t)wv; B1[nt] = (uint32_t)(wv >> 32);             \
        }                                                                     \
        const float* As0 = Db0 + s * 1216 + g2;                               \
        MMA_TILE(As0 + 16 * (MT0), C0, L0, H0);                               \
        MMA_TILE(As0 + 16 * (MT1), C1, L1, H1);                               \
        MMA_TILE(As0 + 16 * (MT2), C2, L2, H2);                               \
        const float* As1 = Db1 + s * 1216 + g2;                               \
        MMA_TILE(As1 + 16 * (MT0), (C0) + 12, L0, H0);                        \
        MMA_TILE(As1 + 16 * (MT1), (C1) + 12, L1, H1);                        \
        MMA_TILE(As1 + 16 * (MT2), (C2) + 12, L2, H2);                        \
    }                                                                         \
} while (0)

__device__ __forceinline__ void accW(unsigned long long* p3, float act, int idx) {
    unsigned long long a2;
    asm("mov.b64 %0, {%1, %2};" : "=l"(a2) : "f"(act), "f"(act));
    uint2 wp = __ldg(g_wfP + idx);
    uint32_t wq = __ldg(g_wfQ + idx);
    unsigned long long w64;
    asm("mov.b64 %0, {%1, %2};" : "=l"(w64) : "r"(wp.x << 16), "r"(wp.x & 0xffff0000u));
    asm("fma.rn.f32x2 %0, %1, %2, %0;" : "+l"(p3[0]) : "l"(a2), "l"(w64));
    asm("mov.b64 %0, {%1, %2};" : "=l"(w64) : "r"(wp.y << 16), "r"(wp.y & 0xffff0000u));
    asm("fma.rn.f32x2 %0, %1, %2, %0;" : "+l"(p3[1]) : "l"(a2), "l"(w64));
    asm("mov.b64 %0, {%1, %2};" : "=l"(w64) : "r"(wq << 16), "r"(wq & 0xffff0000u));
    asm("fma.rn.f32x2 %0, %1, %2, %0;" : "+l"(p3[2]) : "l"(a2), "l"(w64));
}

#define DEN_TILE(MT, NTLO, NTHI, CB) do {                                     \
    _Pragma("unroll")                                                         \
    for (int nt = (NTLO); nt < (NTHI); ++nt) {                                \
        float* c = C[(CB) + nt - (NTLO)];                                     \
        int co = 8 * nt + 2 * tg;                                             \
        int base = (((MT) * 5 + nt) * 4) * 32 + l;                            \
        accW(p3, frelu(c2s[co] + c[0]), base);                                \
        accW(p3, frelu(c2s[co + 1] + c[1]), base + 32);                       \
        accW(p3, frelu(c2s[co] + c[2]), base + 64);                           \
        accW(p3, frelu(c2s[co + 1] + c[3]), base + 96);                       \
    }                                                                         \
} while (0)

__global__ void __launch_bounds__(128, 3) patch_kernel(
    const float* __restrict__ img, const float* __restrict__ lab,
    const float* __restrict__ w1, const float* __restrict__ b1,
    const float* __restrict__ d1b)
{
    extern __shared__ float smem[];
    float* w2p   = smem;
    float* w1_s  = smem + 17144;
    float* b1_s  = smem + 17504;
    float* c2s   = smem + 17544;
    float* red_s = smem + 17584;

    const int t = threadIdx.x;
    const int n0 = 2 * blockIdx.x;

    const uint32_t w2p_u = smem_u32(w2p);

    // stream ALL conv2 fragment weights (36.3KB) once
    #pragma unroll
    for (int r = 0; r < 18; ++r) {
        int k = t + 128 * r;
        if (k < 2268) cp_async16(w2p_u + k * 16, (const float4*)g_w2p + k);
    }
    CP_COMMIT();

    for (int k = t; k < 360; k += 128) w1_s[k] = w1[k];
    if (t < 40) { b1_s[t] = b1[t]; c2s[t] = g_c2[t]; }
    for (int k = t; k < 696; k += 128) smem[16448 + k] = 0.f;   // both tok tiles
    {
        float4* z = (float4*)(smem + 9088);
        #pragma unroll
        for (int r = 0; r < 15; ++r) {
            int k = t + 128 * r;
            if (k < 1840) z[k] = make_float4(0.f, 0.f, 0.f, 0.f);
        }
    }
    __syncthreads();

    // tokens (central 8x8; threads 0-63 -> patch0, 64-127 -> patch1) + label sums
    {
        int pat = t >> 6;
        int np = n0 + pat;
        int gp = np >> 10;
        int ijp = np & 1023;
        int ip = ijp >> 5, jp = ijp & 31;
        int r0p = 16 * ip + 8 * (gp & 1) - 4;
        int c0p = 16 * jp + 8 * (gp >> 1) - 4;
        int q6 = t & 63;
        int py = 4 + (q6 >> 3), px = 4 + (q6 & 7);
        int gr = r0p + py, gc = c0p + px;
        float* tok_p = smem + 16448 + pat * 348;
        tok_p[(py + 1) * 18 + px + 1] = __ldg(img + gr * 512 + gc);
        float sum_lp = __ldg(lab + gr * 512 + gc);
        #pragma unroll
        for (int o = 16; o; o >>= 1)
            sum_lp += __shfl_down_sync(0xffffffffu, sum_lp, o);
        if ((t & 31) == 0) red_s[t >> 5] = sum_lp;
    }
    __syncthreads();
    if (t == 0)  g_label[n0]     = dround(dround((red_s[0] + red_s[1]) / 64.f));
    if (t == 64) g_label[n0 + 1] = dround(dround((red_s[2] + red_s[3]) / 64.f));

    // ---- conv1 delta for both patches -> bf16x2 channel-pair planes ----
    if (t < 100) {
        int rr = 3 + t / 10, cc = 3 + t - 10 * (t / 10);
        int dpos = (rr - 2) * 12 + (cc - 2);
        #pragma unroll
        for (int pat = 0; pat < 2; ++pat) {
            const float* tok_p = smem + 16448 + pat * 348;
            float* Dgp = smem + 9104 + pat * 3680;
            float t9[9];
            #pragma unroll
            for (int k = 0; k < 9; k++) t9[k] = tok_p[(rr + k / 3) * 18 + (cc + k % 3)];
            #pragma unroll 4
            for (int pr = 0; pr < 20; pr++) {
                float sA = 0.f, sB = 0.f;
                #pragma unroll
                for (int k = 0; k < 9; k++) {
                    sA = fmaf(t9[k], w1_s[k * 40 + 2 * pr], sA);
                    sB = fmaf(t9[k], w1_s[k * 40 + 2 * pr + 1], sB);
                }
                float bA = b1_s[2 * pr], bB = b1_s[2 * pr + 1];
                *(uint32_t*)(Dgp + pr * 152 + dpos) =
                    pack_bf16x2(frelu(bA + sA) - frelu(bA), frelu(bB + sB) - frelu(bB));
            }
        }
    }

    CP_WAIT(0);
    __syncthreads();

    // ---- conv2 delta: 4 warps, each covers its MT set for BOTH patches ----
    const int w4 = t >> 5, l = t & 31;
    const int g2 = l >> 2, tg = l & 3;
    const int tg152 = tg * 152;
    float* Dg0b = smem + 9104;
    float* Dg1b = smem + 9104 + 3680;

    float C[24][4];
    #pragma unroll
    for (int a = 0; a < 24; a++)
        #pragma unroll
        for (int b = 0; b < 4; b++) C[a][b] = 0.f;

    if (w4 == 0) {
        for (int tap = 0; tap < 9; ++tap) {
            const float* wb = w2p + tap * 1008;
            const int off = (tap / 3 - 1) * 12 + (tap % 3) - 1;
            const float* Db0 = Dg0b + off;
            const float* Db1 = Dg1b + off;
            KSTEPS2(0, 0, 5, 0,   1, 0, 5, 5,   2, 0, 2, 10);
        }
    } else if (w4 == 1) {
        for (int tap = 0; tap < 9; ++tap) {
            const float* wb = w2p + tap * 1008;
            const int off = (tap / 3 - 1) * 12 + (tap % 3) - 1;
            const float* Db0 = Dg0b + off;
            const float* Db1 = Dg1b + off;
            KSTEPS2(2, 2, 5, 0,   3, 0, 5, 3,   4, 0, 3, 8);
        }
    } else if (w4 == 2) {
        for (int tap = 0; tap < 9; ++tap) {
            const float* wb = w2p + tap * 1008;
            const int off = (tap / 3 - 1) * 12 + (tap % 3) - 1;
            const float* Db0 = Dg0b + off;
            const float* Db1 = Dg1b + off;
            KSTEPS2(4, 3, 5, 0,   5, 0, 5, 2,   6, 0, 4, 7);
        }
    } else {
        for (int tap = 0; tap < 9; ++tap) {
            const float* wb = w2p + tap * 1008;
            const int off = (tap / 3 - 1) * 12 + (tap % 3) - 1;
            const float* Db0 = Dg0b + off;
            const float* Db1 = Dg1b + off;
            KSTEPS2(6, 4, 5, 0,   7, 0, 5, 1,   8, 0, 5, 6);
        }
    }

    // ---- dense1 from accumulators (bf16 weights), per patch ----
    #pragma unroll
    for (int pat = 0; pat < 2; ++pat) {
        unsigned long long p3[3] = {0ull, 0ull, 0ull};
        const int cb = 12 * pat;
        if (w4 == 0) {
            DEN_TILE(0, 0, 5, cb); DEN_TILE(1, 0, 5, cb + 5); DEN_TILE(2, 0, 2, cb + 10);
        } else if (w4 == 1) {
            DEN_TILE(2, 2, 5, cb); DEN_TILE(3, 0, 5, cb + 3); DEN_TILE(4, 0, 3, cb + 8);
        } else if (w4 == 2) {
            DEN_TILE(4, 3, 5, cb); DEN_TILE(5, 0, 5, cb + 2); DEN_TILE(6, 0, 4, cb + 7);
        } else {
            DEN_TILE(6, 4, 5, cb); DEN_TILE(7, 0, 5, cb + 1); DEN_TILE(8, 0, 5, cb + 6);
        }
        float part[6];
        #pragma unroll
        for (int k2 = 0; k2 < 3; k2++)
            asm("mov.b64 {%0, %1}, %2;" : "=f"(part[2 * k2]), "=f"(part[2 * k2 + 1]) : "l"(p3[k2]));
        #pragma unroll
        for (int k = 0; k < 6; k++)
            #pragma unroll
            for (int o = 16; o; o >>= 1) part[k] += __shfl_down_sync(0xffffffffu, part[k], o);
        if (l == 0) {
            #pragma unroll
            for (int k = 0; k < 6; k++) red_s[8 + pat * 24 + w4 * 6 + k] = part[k];
        }
    }
    __syncthreads();
    if (t < 8) {
        float val = 0.f;
        if (t < 6) {
            const float* rb = red_s + 8;
            float s = rb[t] + rb[6 + t] + rb[12 + t] + rb[18 + t];
            val = frelu(s + g_extk[t] + d1b[t]);
        }
        g_nodes[n0 * 8 + t] = val;
    } else if (t >= 64 && t < 72) {
        int k = t - 64;
        float val = 0.f;
        if (k < 6) {
            const float* rb = red_s + 32;
            float s = rb[k] + rb[6 + k] + rb[12 + k] + rb[18 + k];
            val = frelu(s + g_extk[k] + d1b[k]);
        }
        g_nodes[(n0 + 1) * 8 + k] = val;
    }
}

// ---------------- kernel 2: fused edge MLP + agg + node MLP + CE ----------------
__global__ void __launch_bounds__(128) graph_kernel(
    const int* __restrict__ snd,
    const float* __restrict__ we0, const float* __restrict__ be0,
    const float* __restrict__ we1, const float* __restrict__ be1,
    const float* __restrict__ we2, const float* __restrict__ be2,
    const float* __restrict__ we3, const float* __restrict__ be3,
    const float* __restrict__ wn0, const float* __restrict__ bn0,
    const float* __restrict__ wn1, const float* __restrict__ bn1,
    const float* __restrict__ wn2, const float* __restrict__ bn2,
    const float* __restrict__ wn3, const float* __restrict__ bn3,
    const float* __restrict__ wout, const float* __restrict__ bout,
    float* __restrict__ out)
{
    __shared__ float sw[422];
    int t = threadIdx.x;
    {
        const float* srcs[18] = {we0, be0, we1, be1, we2, be2, we3, be3,
                                 wn0, bn0, wn1, bn1, wn2, bn2, wn3, bn3, wout, bout};
        const int sizes[18] = {65, 5, 25, 5, 25, 5, 50, 10, 85, 5, 25, 5, 25, 5, 50, 10, 20, 2};
        int off = 0;
        #pragma unroll
        for (int a = 0; a < 18; a++) {
            for (int k = t; k < sizes[a]; k += 128) sw[off + k] = __ldg(srcs[a] + k);
            off += sizes[a];
        }
    }
    __syncthreads();
    const float* s_we0 = sw;        const float* s_be0 = sw + 65;
    const float* s_we1 = sw + 70;   const float* s_be1 = sw + 95;
    const float* s_we2 = sw + 100;  const float* s_be2 = sw + 125;
    const float* s_we3 = sw + 130;  const float* s_be3 = sw + 180;
    const float* s_wn0 = sw + 190;  const float* s_bn0 = sw + 275;
    const float* s_wn1 = sw + 280;  const float* s_bn1 = sw + 305;
    const float* s_wn2 = sw + 310;  const float* s_bn2 = sw + 335;
    const float* s_wn3 = sw + 340;  const float* s_bn3 = sw + 390;
    const float* s_wout = sw + 400; const float* s_bout = sw + 420;

    int n = blockIdx.x * 32 + (t >> 2);
    int q = t & 3;

    int sv = g_slot[n * 4 + q];
    g_slot[n * 4 + q] = 0;

    float4 r0v = *(const float4*)(g_nodes + n * 8);
    float2 r1v = *(const float2*)(g_nodes + n * 8 + 4);

    float ef[10];
    #pragma unroll
    for (int k = 0; k < 10; k++) ef[k] = 0.f;

    if (sv) {
        int e = sv - 1;
        int s = snd[e];
        float4 s0v = *(const float4*)(g_nodes + s * 8);
        float2 s1v = *(const float2*)(g_nodes + s * 8 + 4);
        float x[13];
        x[0] = s0v.x; x[1] = s0v.y; x[2] = s0v.z; x[3] = s0v.w; x[4] = s1v.x; x[5] = s1v.y;
        x[6] = r0v.x; x[7] = r0v.y; x[8] = r0v.z; x[9] = r0v.w; x[10] = r1v.x; x[11] = r1v.y;
        x[12] = 1.f;

        float h0[5], h1[5], h2[5];
        #pragma unroll
        for (int k = 0; k < 5; k++) {
            float a = s_be0[k];
            #pragma unroll
            for (int i2 = 0; i2 < 13; i2++) a = fmaf(x[i2], s_we0[i2 * 5 + k], a);
            h0[k] = frelu(a);
        }
        #pragma unroll
        for (int k = 0; k < 5; k++) {
            float a = s_be1[k];
            #pragma unroll
            for (int i2 = 0; i2 < 5; i2++) a = fmaf(h0[i2], s_we1[i2 * 5 + k], a);
            h1[k] = frelu(a);
        }
        #pragma unroll
        for (int k = 0; k < 5; k++) {
            float a = s_be2[k];
            #pragma unroll
            for (int i2 = 0; i2 < 5; i2++) a = fmaf(h1[i2], s_we2[i2 * 5 + k], a);
            h2[k] = frelu(a);
        }
        #pragma unroll
        for (int k = 0; k < 10; k++) {
            float a = s_be3[k];
            #pragma unroll
            for (int i2 = 0; i2 < 5; i2++) a = fmaf(h2[i2], s_we3[i2 * 10 + k], a);
            ef[k] = a;
        }
    }
    #pragma unroll
    for (int k = 0; k < 10; k++) {
        ef[k] += __shfl_xor_sync(0xffffffffu, ef[k], 1);
        ef[k] += __shfl_xor_sync(0xffffffffu, ef[k], 2);
    }
    if (q != 0) return;

    float x[17];
    x[0] = r0v.x; x[1] = r0v.y; x[2] = r0v.z; x[3] = r0v.w; x[4] = r1v.x; x[5] = r1v.y;
    #pragma unroll
    for (int k = 0; k < 10; k++) x[6 + k] = ef[k];
    x[16] = 1.f;

    float h0[5], h1[5], h2[5], o[10];
    #pragma unroll
    for (int k = 0; k < 5; k++) {
        float a = s_bn0[k];
        #pragma unroll
        for (int i2 = 0; i2 < 17; i2++) a = fmaf(x[i2], s_wn0[i2 * 5 + k], a);
        h0[k] = frelu(a);
    }
    #pragma unroll
    for (int k = 0; k < 5; k++) {
        float a = s_bn1[k];
        #pragma unroll
        for (int i2 = 0; i2 < 5; i2++) a = fmaf(h0[i2], s_wn1[i2 * 5 + k], a);
        h1[k] = frelu(a);
    }
    #pragma unroll
    for (int k = 0; k < 5; k++) {
        float a = s_bn2[k];
        #pragma unroll
        for (int i2 = 0; i2 < 5; i2++) a = fmaf(h1[i2], s_wn2[i2 * 5 + k], a);
        h2[k] = frelu(a);
    }
    #pragma unroll
    for (int k = 0; k < 10; k++) {
        float a = s_bn3[k];
        #pragma unroll
        for (int i2 = 0; i2 < 5; i2++) a = fmaf(h2[i2], s_wn3[i2 * 10 + k], a);
        o[k] = a;
    }
    float l0 = s_bout[0], l1 = s_bout[1];
    #pragma unroll
    for (int i2 = 0; i2 < 10; i2++) {
        l0 = fmaf(o[i2], s_wout[i2 * 2 + 0], l0);
        l1 = fmaf(o[i2], s_wout[i2 * 2 + 1], l1);
    }
    float m = fmaxf(l0, l1);
    float lse = m + logf(expf(l0 - m) + expf(l1 - m));
    float sv2 = g_label[n];
    out[n] = -((1.f - sv2) * (l0 - lse) + sv2 * (l1 - lse));
}

// ---------------- launch ----------------
extern "C" void kernel_launch(void* const* d_in, const int* in_sizes, int n_in,
                              void* d_out, int out_size)
{
    const float* img = (const float*)d_in[0];
    const float* lab = (const float*)d_in[1];
    const float* w1  = (const float*)d_in[3];
    const float* b1  = (const float*)d_in[4];
    const float* w2  = (const float*)d_in[5];
    const float* b2  = (const float*)d_in[6];
    const float* d1w = (const float*)d_in[7];
    const float* d1b = (const float*)d_in[8];
    const float* we0 = (const float*)d_in[9];
    const float* be0 = (const float*)d_in[10];
    const float* we1 = (const float*)d_in[11];
    const float* be1 = (const float*)d_in[12];
    const float* we2 = (const float*)d_in[13];
    const float* be2 = (const float*)d_in[14];
    const float* we3 = (const float*)d_in[15];
    const float* be3 = (const float*)d_in[16];
    const float* wn0 = (const float*)d_in[17];
    const float* bn0 = (const float*)d_in[18];
    const float* wn1 = (const float*)d_in[19];
    const float* bn1 = (const float*)d_in[20];
    const float* wn2 = (const float*)d_in[21];
    const float* bn2 = (const float*)d_in[22];
    const float* wn3 = (const float*)d_in[23];
    const float* bn3 = (const float*)d_in[24];
    const float* wout = (const float*)d_in[25];
    const float* bout = (const float*)d_in[26];
    const int* snd = (const int*)d_in[27];
    const int* rcv = (const int*)d_in[28];
    int E = in_sizes[27];

    int smem_bytes = K1_SMEM_FLOATS * (int)sizeof(float);
    static int configured = -1;
    if (configured != smem_bytes) {
        cudaFuncSetAttribute(patch_kernel, cudaFuncAttributeMaxDynamicSharedMemorySize, smem_bytes);
        configured = smem_bytes;
    }

    int nblk = 136 + (E + 127) / 128;
    pre_a<<<nblk, 128>>>(b1, w2, d1w, rcv, E);
    pre_b<<<1, 128>>>(b2);
    patch_kernel<<<2048, 128, smem_bytes>>>(img, lab, w1, b1, d1b);
    graph_kernel<<<128, 128>>>(snd, we0, be0, we1, be1, we2, be2, we3, be3,
                               wn0, bn0, wn1, bn1, wn2, bn2, wn3, bn3,
                               wout, bout, (float*)d_out);

    (void)n_in; (void)out_size;
}

// round 15
// speedup vs baseline: 1.2972x; 1.2972x over previous
#include <cuda_runtime.h>
#include <math.h>
#include <stdint.h>

#define TWO_PI_F 6.2831853071795864769f

// ---------------- scratch ----------------
__device__ float g_nodes[4096 * 8];        // padded to 8 floats/node
__device__ float g_label[4096];
__device__ int   g_slot[4096 * 4];         // slot[n*4+L] = edge_id+1, 0=empty (self-resetting)
// per-launch precompute
__device__ float g_T[360];
__device__ float g_Wc[2160];
__device__ float g_c2[40];
__device__ float g_extk[6];
__device__ unsigned int g_w2p[9072];       // conv2 weights, bf16 fragment-packed
__device__ uint2 g_wfP[5760];              // dense1 weights k0..k3, bf16x2 pairs
__device__ unsigned int g_wfQ[5760];       // dense1 weights k4..k5, bf16x2

__device__ __forceinline__ float frelu(float x) { return x > 0.f ? x : 0.f; }
__device__ __forceinline__ float dround(float x) {
    return x - sinf(x * TWO_PI_F) / TWO_PI_F;
}
__device__ __forceinline__ uint32_t pack_bf16x2(float lo, float hi) {
    uint32_t v; asm("cvt.rn.bf16x2.f32 %0, %1, %2;" : "=r"(v) : "f"(hi), "f"(lo)); return v;
}
__device__ __forceinline__ uint32_t smem_u32(const void* p) {
    uint32_t a;
    asm("{ .reg .u64 t; cvta.to.shared.u64 t, %1; cvt.u32.u64 %0, t; }" : "=r"(a) : "l"(p));
    return a;
}
__device__ __forceinline__ void cp_async16(uint32_t dst, const void* src) {
    asm volatile("cp.async.cg.shared.global [%0], [%1], 16;" :: "r"(dst), "l"(src));
}
#define CP_COMMIT() asm volatile("cp.async.commit_group;")
#define CP_WAIT(n)  asm volatile("cp.async.wait_group %0;" :: "n"(n))

// ---------------- kernel A1: fully parallel precompute ----------------
__global__ void __launch_bounds__(128) pre_a(
    const float* __restrict__ b1, const float* __restrict__ w2,
    const float* __restrict__ d1w, const int* __restrict__ rcv, int E)
{
    const int t = threadIdx.x;
    const int b = blockIdx.x;
    if (b < 3) {
        int item = b * 128 + t;
        if (item < 360) {
            int tap = item / 40, co = item - 40 * tap;
            float s = 0.f;
            #pragma unroll 8
            for (int ci = 0; ci < 40; ci++)
                s = fmaf(frelu(b1[ci]), __ldg(w2 + tap * 1600 + ci * 40 + co), s);
            g_T[item] = s;
        }
        return;
    }
    if (b < 20) {
        int idx = (b - 3) * 128 + t;
        if (idx < 2160) {
            int cls = idx / 240;
            int rem = idx - 240 * cls;
            int co = rem / 6, k = rem - 6 * co;
            int yc = cls / 3, xc = cls - 3 * yc;
            float s = 0.f;
            for (int p = 0; p < 256; ++p) {
                int y = p >> 4, x = p & 15;
                if (y >= 2 && y <= 13 && x >= 2 && x <= 13) continue;
                int pyc = (y == 0) ? 0 : (y == 15 ? 2 : 1);
                int pxc = (x == 0) ? 0 : (x == 15 ? 2 : 1);
                if (pyc == yc && pxc == xc)
                    s += __ldg(d1w + (p * 40 + co) * 6 + k);
            }
            g_Wc[idx] = s;
        }
        return;
    }
    if (b < 91) {
        int idx = (b - 20) * 128 + t;
        if (idx < 9072) {
            int blk = idx / 84, r = idx - 84 * blk;
            uint32_t v = 0;
            if (r < 80) {
                int n = r >> 1, h = r & 1;
                int tg = blk & 3, sb = blk >> 2;
                int s = sb % 3, tap = sb / 3;
                int ci0 = 16 * s + 2 * tg + 8 * h;
                float lo = (ci0 < 40)     ? __ldg(w2 + tap * 1600 + ci0 * 40 + n)       : 0.f;
                float hi = (ci0 + 1 < 40) ? __ldg(w2 + tap * 1600 + (ci0 + 1) * 40 + n) : 0.f;
                v = pack_bf16x2(lo, hi);
            }
            g_w2p[idx] = v;
        }
        return;
    }
    if (b < 136) {
        int idx = (b - 91) * 128 + t;
        if (idx < 5760) {
            int l = idx & 31, e = (idx >> 5) & 3, T = idx >> 7;
            int MT = T / 5, nt = T - 5 * MT;
            int g2v = l >> 2, tgv = l & 3;
            int p = 16 * MT + g2v + ((e >= 2) ? 8 : 0);
            int co = 8 * nt + 2 * tgv + (e & 1);
            int oy = 2 + p / 12, ox = 2 + p % 12;
            const float* wr = d1w + ((oy * 16 + ox) * 40 + co) * 6;
            g_wfP[idx] = make_uint2(pack_bf16x2(wr[0], wr[1]), pack_bf16x2(wr[2], wr[3]));
            g_wfQ[idx] = pack_bf16x2(wr[4], wr[5]);
        }
        return;
    }
    int e = (b - 136) * 128 + t;
    if (e < E) {
        int r = rcv[e];
        g_slot[r * 4 + ((e / 4032) & 3)] = e + 1;
    }
}

// ---------------- kernel A2: tiny dependent stage (c2, E, extk) ----------------
__global__ void __launch_bounds__(128) pre_b(const float* __restrict__ b2)
{
    const int t = threadIdx.x;
    __shared__ float E[360];
    __shared__ float P[8][6];
    if (t < 40) {
        float s = __ldg(b2 + t);
        #pragma unroll
        for (int tap = 0; tap < 9; tap++) s += g_T[tap * 40 + t];
        g_c2[t] = s;
    }
    for (int item = t; item < 360; item += 128) {
        int cls = item / 40, co = item - 40 * cls;
        int yc = cls / 3, xc = cls - 3 * yc;
        float s = __ldg(b2 + co);
        #pragma unroll
        for (int tap = 0; tap < 9; tap++) {
            int dy = tap / 3, dx = tap % 3;
            bool vy = !((yc == 0 && dy == 0) || (yc == 2 && dy == 2));
            bool vx = !((xc == 0 && dx == 0) || (xc == 2 && dx == 2));
            if (vy && vx) s += g_T[tap * 40 + co];
        }
        E[item] = frelu(s);
    }
    __syncthreads();
    if (t < 48) {
        int k = t % 6, c = t / 6;
        float acc = 0.f;
        #pragma unroll 5
        for (int m = 0; m < 45; ++m) {
            int item = c * 45 + m;
            acc = fmaf(E[item], g_Wc[item * 6 + k], acc);
        }
        P[c][k] = acc;
    }
    __syncthreads();
    if (t < 6) {
        float s = 0.f;
        #pragma unroll
        for (int c = 0; c < 8; c++) s += P[c][t];
        g_extk[t] = s;
    }
}

// ---------------- kernel 1: dual-patch, bf16 MMA, resident weights ----------------
#define K1_SMEM_FLOATS 17648

#define MMA_TILE(Ap, CB, NTLO, NTHI) do {                                     \
    uint32_t a0 = __float_as_uint((Ap)[tg152]);                               \
    uint32_t a1 = __float_as_uint((Ap)[tg152 + 8]);                           \
    uint32_t a2 = __float_as_uint((Ap)[tg152 + 608]);                         \
    uint32_t a3 = __float_as_uint((Ap)[tg152 + 616]);                         \
    _Pragma("unroll")                                                         \
    for (int nt = (NTLO); nt < (NTHI); ++nt) {                                \
        float* c = C[(CB) + nt - (NTLO)];                                     \
        asm("mma.sync.aligned.m16n8k16.row.col.f32.bf16.bf16.f32 "            \
            "{%0,%1,%2,%3}, {%4,%5,%6,%7}, {%8,%9}, {%0,%1,%2,%3};"           \
            : "+f"(c[0]), "+f"(c[1]), "+f"(c[2]), "+f"(c[3])                  \
            : "r"(a0), "r"(a1), "r"(a2), "r"(a3), "r"(B0[nt]), "r"(B1[nt]));  \
    }                                                                         \
} while (0)

#define KSTEPS(MT0, L0, H0, C0, MT1, L1, H1, C1, MT2, L2, H2, C2) do {        \
    _Pragma("unroll")                                                         \
    for (int s = 0; s < 3; ++s) {                                             \
        const float* wk = wb + s * 336 + tg * 84 + 2 * g2;                    \
        uint32_t B0[5], B1[5];                                                \
        _Pragma("unroll")                                                     \
        for (int nt = 0; nt < 5; ++nt) {                                      \
            unsigned long long wv = *(const unsigned long long*)(wk + 16 * nt); \
            B0[nt] = (uint32_t)wv; B1[nt] = (uint32_t)(wv >> 32);             \
        }                                                                     \
        const float* As = Db + s * 1216 + g2;                                 \
        MMA_TILE(As + 16 * (MT0), C0, L0, H0);                                \
        MMA_TILE(As + 16 * (MT1), C1, L1, H1);                                \
        MMA_TILE(As + 16 * (MT2), C2, L2, H2);                                \
    }                                                                         \
} while (0)

// bf16 dense weights: unpack via bit ops (exact), f32x2 accumulate
__device__ __forceinline__ void accW(unsigned long long* p3, float act, int idx) {
    unsigned long long a2;
    asm("mov.b64 %0, {%1, %2};" : "=l"(a2) : "f"(act), "f"(act));
    uint2 wp = __ldg(g_wfP + idx);
    uint32_t wq = __ldg(g_wfQ + idx);
    unsigned long long w64;
    asm("mov.b64 %0, {%1, %2};" : "=l"(w64) : "r"(wp.x << 16), "r"(wp.x & 0xffff0000u));
    asm("fma.rn.f32x2 %0, %1, %2, %0;" : "+l"(p3[0]) : "l"(a2), "l"(w64));
    asm("mov.b64 %0, {%1, %2};" : "=l"(w64) : "r"(wp.y << 16), "r"(wp.y & 0xffff0000u));
    asm("fma.rn.f32x2 %0, %1, %2, %0;" : "+l"(p3[1]) : "l"(a2), "l"(w64));
    asm("mov.b64 %0, {%1, %2};" : "=l"(w64) : "r"(wq << 16), "r"(wq & 0xffff0000u));
    asm("fma.rn.f32x2 %0, %1, %2, %0;" : "+l"(p3[2]) : "l"(a2), "l"(w64));
}

#define DEN_TILE(MT, NTLO, NTHI, CB) do {                                     \
    _Pragma("unroll")                                                         \
    for (int nt = (NTLO); nt < (NTHI); ++nt) {                                \
        float* c = C[(CB) + nt - (NTLO)];                                     \
        int co = 8 * nt + 2 * tg;                                             \
        int base = (((MT) * 5 + nt) * 4) * 32 + l;                            \
        accW(p3, frelu(c2s[co] + c[0]), base);                                \
        accW(p3, frelu(c2s[co + 1] + c[1]), base + 32);                       \
        accW(p3, frelu(c2s[co] + c[2]), base + 64);                           \
        accW(p3, frelu(c2s[co + 1] + c[3]), base + 96);                       \
    }                                                                         \
} while (0)

__global__ void __launch_bounds__(256, 3) patch_kernel(
    const float* __restrict__ img, const float* __restrict__ lab,
    const float* __restrict__ w1, const float* __restrict__ b1,
    const float* __restrict__ d1b)
{
    extern __shared__ float smem[];
    float* w2p   = smem;
    float* w1_s  = smem + 17144;
    float* b1_s  = smem + 17504;
    float* c2s   = smem + 17544;
    float* red_s = smem + 17584;

    const int t  = threadIdx.x;
    const int wg = t >> 7;
    const int wt = t & 127;
    float* tok_s = smem + 16448 + wg * 348;
    float* Dg    = smem + 9104 + wg * 3680;

    const int n = 2 * blockIdx.x + wg;
    const int g = n >> 10;
    const int ij = n & 1023;
    const int i = ij >> 5, j = ij & 31;
    const int sx = g & 1, sy = g >> 1;
    const int r0 = 16 * i + 8 * sx - 4;
    const int c0 = 16 * j + 8 * sy - 4;

    const uint32_t w2p_u = smem_u32(w2p);

    // stream ALL conv2 fragment weights (36.3KB) once
    #pragma unroll
    for (int r = 0; r < 9; ++r) {
        int k = t + 256 * r;
        if (k < 2268) cp_async16(w2p_u + k * 16, (const float4*)g_w2p + k);
    }
    CP_COMMIT();

    for (int k = t; k < 360; k += 256) w1_s[k] = w1[k];
    if (t < 40) { b1_s[t] = b1[t]; c2s[t] = g_c2[t]; }
    if (wt < 128) for (int k = wt; k < 324; k += 128) tok_s[k] = 0.f;
    {
        float4* z = (float4*)(smem + 9088);
        #pragma unroll
        for (int r = 0; r < 8; ++r) {
            int k = t + 256 * r;
            if (k < 1840) z[k] = make_float4(0.f, 0.f, 0.f, 0.f);
        }
    }
    __syncthreads();

    // tokens (central 8x8 only — mask is exactly the central cell) + label sum
    float sum_lp = 0.f;
    if (wt < 64) {
        int py = 4 + (wt >> 3), px = 4 + (wt & 7);
        int gr = r0 + py, gc = c0 + px;          // always in-bounds
        tok_s[(py + 1) * 18 + px + 1] = __ldg(img + gr * 512 + gc);
        sum_lp = __ldg(lab + gr * 512 + gc);
    }
    #pragma unroll
    for (int o = 16; o; o >>= 1)
        sum_lp += __shfl_down_sync(0xffffffffu, sum_lp, o);
    if (wt < 64 && (wt & 31) == 0) red_s[wg * 2 + (wt >> 5)] = sum_lp;
    __syncthreads();
    if (wt == 0) {
        float sl = red_s[wg * 2] + red_s[wg * 2 + 1];
        g_label[n] = dround(dround(sl / 64.f));
    }

    // ---- conv1 delta -> bf16x2 channel-pair planes ----
    if (wt < 100) {
        int rr = 3 + wt / 10, cc = 3 + wt - 10 * (wt / 10);
        float t9[9];
        #pragma unroll
        for (int k = 0; k < 9; k++) t9[k] = tok_s[(rr + k / 3) * 18 + (cc + k % 3)];
        int dpos = (rr - 2) * 12 + (cc - 2);
        #pragma unroll 4
        for (int pr = 0; pr < 20; pr++) {
            float sA = 0.f, sB = 0.f;
            #pragma unroll
            for (int k = 0; k < 9; k++) {
                sA = fmaf(t9[k], w1_s[k * 40 + 2 * pr], sA);
                sB = fmaf(t9[k], w1_s[k * 40 + 2 * pr + 1], sB);
            }
            float bA = b1_s[2 * pr], bB = b1_s[2 * pr + 1];
            float dA = frelu(bA + sA) - frelu(bA);
            float dB = frelu(bB + sB) - frelu(bB);
            *(uint32_t*)(Dg + pr * 152 + dpos) = pack_bf16x2(dA, dB);
        }
    }

    CP_WAIT(0);
    __syncthreads();   // D16 + weights visible

    // ---- conv2 delta via bf16 mma: 9 taps straight through, no syncs ----
    const int w4 = (t >> 5) & 3, l = t & 31;
    const int g2 = l >> 2, tg = l & 3;
    const int tg152 = tg * 152;

    float C[12][4];
    #pragma unroll
    for (int a = 0; a < 12; a++)
        #pragma unroll
        for (int b = 0; b < 4; b++) C[a][b] = 0.f;

    if (w4 == 0) {
        for (int tap = 0; tap < 9; ++tap) {
            const float* wb = w2p + tap * 1008;
            const float* Db = Dg + (tap / 3 - 1) * 12 + (tap % 3) - 1;
            KSTEPS(0, 0, 5, 0,   1, 0, 5, 5,   2, 0, 2, 10);
        }
    } else if (w4 == 1) {
        for (int tap = 0; tap < 9; ++tap) {
            const float* wb = w2p + tap * 1008;
            const float* Db = Dg + (tap / 3 - 1) * 12 + (tap % 3) - 1;
            KSTEPS(2, 2, 5, 0,   3, 0, 5, 3,   4, 0, 3, 8);
        }
    } else if (w4 == 2) {
        for (int tap = 0; tap < 9; ++tap) {
            const float* wb = w2p + tap * 1008;
            const float* Db = Dg + (tap / 3 - 1) * 12 + (tap % 3) - 1;
            KSTEPS(4, 3, 5, 0,   5, 0, 5, 2,   6, 0, 4, 7);
        }
    } else {
        for (int tap = 0; tap < 9; ++tap) {
            const float* wb = w2p + tap * 1008;
            const float* Db = Dg + (tap / 3 - 1) * 12 + (tap % 3) - 1;
            KSTEPS(6, 4, 5, 0,   7, 0, 5, 1,   8, 0, 5, 6);
        }
    }

    // ---- dense1 straight from accumulators (bf16 weights) ----
    unsigned long long p3[3] = {0ull, 0ull, 0ull};
    if (w4 == 0) {
        DEN_TILE(0, 0, 5, 0); DEN_TILE(1, 0, 5, 5); DEN_TILE(2, 0, 2, 10);
    } else if (w4 == 1) {
        DEN_TILE(2, 2, 5, 0); DEN_TILE(3, 0, 5, 3); DEN_TILE(4, 0, 3, 8);
    } else if (w4 == 2) {
        DEN_TILE(4, 3, 5, 0); DEN_TILE(5, 0, 5, 2); DEN_TILE(6, 0, 4, 7);
    } else {
        DEN_TILE(6, 4, 5, 0); DEN_TILE(7, 0, 5, 1); DEN_TILE(8, 0, 5, 6);
    }
    float part[6];
    #pragma unroll
    for (int k2 = 0; k2 < 3; k2++)
        asm("mov.b64 {%0, %1}, %2;" : "=f"(part[2 * k2]), "=f"(part[2 * k2 + 1]) : "l"(p3[k2]));
    #pragma unroll
    for (int k = 0; k < 6; k++)
        #pragma unroll
        for (int o = 16; o; o >>= 1) part[k] += __shfl_down_sync(0xffffffffu, part[k], o);
    __syncthreads();
    if (l == 0) {
        #pragma unroll
        for (int k = 0; k < 6; k++) red_s[8 + wg * 24 + w4 * 6 + k] = part[k];
    }
    __syncthreads();
    if (wt < 8) {
        float val = 0.f;
        if (wt < 6) {
            const float* rb = red_s + 8 + wg * 24;
            float s = rb[wt] + rb[6 + wt] + rb[12 + wt] + rb[18 + wt];
            val = frelu(s + g_extk[wt] + d1b[wt]);
        }
        g_nodes[n * 8 + wt] = val;
    }
}

// ---------------- kernel 2: fused edge MLP + agg + node MLP + CE ----------------
__global__ void __launch_bounds__(128) graph_kernel(
    const int* __restrict__ snd,
    const float* __restrict__ we0, const float* __restrict__ be0,
    const float* __restrict__ we1, const float* __restrict__ be1,
    const float* __restrict__ we2, const float* __restrict__ be2,
    const float* __restrict__ we3, const float* __restrict__ be3,
    const float* __restrict__ wn0, const float* __restrict__ bn0,
    const float* __restrict__ wn1, const float* __restrict__ bn1,
    const float* __restrict__ wn2, const float* __restrict__ bn2,
    const float* __restrict__ wn3, const float* __restrict__ bn3,
    const float* __restrict__ wout, const float* __restrict__ bout,
    float* __restrict__ out)
{
    __shared__ float sw[422];
    int t = threadIdx.x;
    {
        const float* srcs[18] = {we0, be0, we1, be1, we2, be2, we3, be3,
                                 wn0, bn0, wn1, bn1, wn2, bn2, wn3, bn3, wout, bout};
        const int sizes[18] = {65, 5, 25, 5, 25, 5, 50, 10, 85, 5, 25, 5, 25, 5, 50, 10, 20, 2};
        int off = 0;
        #pragma unroll
        for (int a = 0; a < 18; a++) {
            for (int k = t; k < sizes[a]; k += 128) sw[off + k] = __ldg(srcs[a] + k);
            off += sizes[a];
        }
    }
    __syncthreads();
    const float* s_we0 = sw;        const float* s_be0 = sw + 65;
    const float* s_we1 = sw + 70;   const float* s_be1 = sw + 95;
    const float* s_we2 = sw + 100;  const float* s_be2 = sw + 125;
    const float* s_we3 = sw + 130;  const float* s_be3 = sw + 180;
    const float* s_wn0 = sw + 190;  const float* s_bn0 = sw + 275;
    const float* s_wn1 = sw + 280;  const float* s_bn1 = sw + 305;
    const float* s_wn2 = sw + 310;  const float* s_bn2 = sw + 335;
    const float* s_wn3 = sw + 340;  const float* s_bn3 = sw + 390;
    const float* s_wout = sw + 400; const float* s_bout = sw + 420;

    int n = blockIdx.x * 32 + (t >> 2);
    int q = t & 3;

    int sv = g_slot[n * 4 + q];
    g_slot[n * 4 + q] = 0;                 // reset for next launch (deterministic)

    float4 r0v = *(const float4*)(g_nodes + n * 8);
    float2 r1v = *(const float2*)(g_nodes + n * 8 + 4);

    float ef[10];
    #pragma unroll
    for (int k = 0; k < 10; k++) ef[k] = 0.f;

    if (sv) {
        int e = sv - 1;
        int s = snd[e];
        float4 s0v = *(const float4*)(g_nodes + s * 8);
        float2 s1v = *(const float2*)(g_nodes + s * 8 + 4);
        float x[13];
        x[0] = s0v.x; x[1] = s0v.y; x[2] = s0v.z; x[3] = s0v.w; x[4] = s1v.x; x[5] = s1v.y;
        x[6] = r0v.x; x[7] = r0v.y; x[8] = r0v.z; x[9] = r0v.w; x[10] = r1v.x; x[11] = r1v.y;
        x[12] = 1.f;

        float h0[5], h1[5], h2[5];
        #pragma unroll
        for (int k = 0; k < 5; k++) {
            float a = s_be0[k];
            #pragma unroll
            for (int i2 = 0; i2 < 13; i2++) a = fmaf(x[i2], s_we0[i2 * 5 + k], a);
            h0[k] = frelu(a);
        }
        #pragma unroll
        for (int k = 0; k < 5; k++) {
            float a = s_be1[k];
            #pragma unroll
            for (int i2 = 0; i2 < 5; i2++) a = fmaf(h0[i2], s_we1[i2 * 5 + k], a);
            h1[k] = frelu(a);
        }
        #pragma unroll
        for (int k = 0; k < 5; k++) {
            float a = s_be2[k];
            #pragma unroll
            for (int i2 = 0; i2 < 5; i2++) a = fmaf(h1[i2], s_we2[i2 * 5 + k], a);
            h2[k] = frelu(a);
        }
        #pragma unroll
        for (int k = 0; k < 10; k++) {
            float a = s_be3[k];
            #pragma unroll
            for (int i2 = 0; i2 < 5; i2++) a = fmaf(h2[i2], s_we3[i2 * 10 + k], a);
            ef[k] = a;
        }
    }
    #pragma unroll
    for (int k = 0; k < 10; k++) {
        ef[k] += __shfl_xor_sync(0xffffffffu, ef[k], 1);
        ef[k] += __shfl_xor_sync(0xffffffffu, ef[k], 2);
    }
    if (q != 0) return;

    float x[17];
    x[0] = r0v.x; x[1] = r0v.y; x[2] = r0v.z; x[3] = r0v.w; x[4] = r1v.x; x[5] = r1v.y;
    #pragma unroll
    for (int k = 0; k < 10; k++) x[6 + k] = ef[k];
    x[16] = 1.f;

    float h0[5], h1[5], h2[5], o[10];
    #pragma unroll
    for (int k = 0; k < 5; k++) {
        float a = s_bn0[k];
        #pragma unroll
        for (int i2 = 0; i2 < 17; i2++) a = fmaf(x[i2], s_wn0[i2 * 5 + k], a);
        h0[k] = frelu(a);
    }
    #pragma unroll
    for (int k = 0; k < 5; k++) {
        float a = s_bn1[k];
        #pragma unroll
        for (int i2 = 0; i2 < 5; i2++) a = fmaf(h0[i2], s_wn1[i2 * 5 + k], a);
        h1[k] = frelu(a);
    }
    #pragma unroll
    for (int k = 0; k < 5; k++) {
        float a = s_bn2[k];
        #pragma unroll
        for (int i2 = 0; i2 < 5; i2++) a = fmaf(h1[i2], s_wn2[i2 * 5 + k], a);
        h2[k] = frelu(a);
    }
    #pragma unroll
    for (int k = 0; k < 10; k++) {
        float a = s_bn3[k];
        #pragma unroll
        for (int i2 = 0; i2 < 5; i2++) a = fmaf(h2[i2], s_wn3[i2 * 10 + k], a);
        o[k] = a;
    }
    float l0 = s_bout[0], l1 = s_bout[1];
    #pragma unroll
    for (int i2 = 0; i2 < 10; i2++) {
        l0 = fmaf(o[i2], s_wout[i2 * 2 + 0], l0);
        l1 = fmaf(o[i2], s_wout[i2 * 2 + 1], l1);
    }
    float m = fmaxf(l0, l1);
    float lse = m + logf(expf(l0 - m) + expf(l1 - m));
    float sv2 = g_label[n];
    out[n] = -((1.f - sv2) * (l0 - lse) + sv2 * (l1 - lse));
}

// ---------------- launch ----------------
extern "C" void kernel_launch(void* const* d_in, const int* in_sizes, int n_in,
                              void* d_out, int out_size)
{
    const float* img = (const float*)d_in[0];
    const float* lab = (const float*)d_in[1];
    const float* w1  = (const float*)d_in[3];
    const float* b1  = (const float*)d_in[4];
    const float* w2  = (const float*)d_in[5];
    const float* b2  = (const float*)d_in[6];
    const float* d1w = (const float*)d_in[7];
    const float* d1b = (const float*)d_in[8];
    const float* we0 = (const float*)d_in[9];
    const float* be0 = (const float*)d_in[10];
    const float* we1 = (const float*)d_in[11];
    const float* be1 = (const float*)d_in[12];
    const float* we2 = (const float*)d_in[13];
    const float* be2 = (const float*)d_in[14];
    const float* we3 = (const float*)d_in[15];
    const float* be3 = (const float*)d_in[16];
    const float* wn0 = (const float*)d_in[17];
    const float* bn0 = (const float*)d_in[18];
    const float* wn1 = (const float*)d_in[19];
    const float* bn1 = (const float*)d_in[20];
    const float* wn2 = (const float*)d_in[21];
    const float* bn2 = (const float*)d_in[22];
    const float* wn3 = (const float*)d_in[23];
    const float* bn3 = (const float*)d_in[24];
    const float* wout = (const float*)d_in[25];
    const float* bout = (const float*)d_in[26];
    const int* snd = (const int*)d_in[27];
    const int* rcv = (const int*)d_in[28];
    int E = in_sizes[27];

    int smem_bytes = K1_SMEM_FLOATS * (int)sizeof(float);
    static int configured = -1;
    if (configured != smem_bytes) {
        cudaFuncSetAttribute(patch_kernel, cudaFuncAttributeMaxDynamicSharedMemorySize, smem_bytes);
        configured = smem_bytes;
    }

    int nblk = 136 + (E + 127) / 128;
    pre_a<<<nblk, 128>>>(b1, w2, d1w, rcv, E);
    pre_b<<<1, 128>>>(b2);
    patch_kernel<<<2048, 256, smem_bytes>>>(img, lab, w1, b1, d1b);
    graph_kernel<<<128, 128>>>(snd, we0, be0, we1, be1, we2, be2, we3, be3,
                               wn0, bn0, wn1, bn1, wn2, bn2, wn3, bn3,
                               wout, bout, (float*)d_out);

    (void)n_in; (void)out_size;
}

// round 16
// speedup vs baseline: 1.3947x; 1.0751x over previous
#include <cuda_runtime.h>
#include <math.h>
#include <stdint.h>

#define TWO_PI_F 6.2831853071795864769f

// ---------------- scratch ----------------
__device__ float g_nodes[4096 * 8];        // padded to 8 floats/node
__device__ float g_label[4096];
__device__ int   g_slot[4096 * 4];         // slot[n*4+L] = edge_id+1, 0=empty (self-resetting)
// per-launch precompute
__device__ float g_T[360];
__device__ float g_Wc[2160];
__device__ float g_c2[40];
__device__ float g_extk[6];
__device__ unsigned int g_w2p[8640];       // conv2 weights, bf16 LANE-INNERMOST fragment order
__device__ uint2 g_wfP[5760];              // dense1 weights k0..k3, bf16x2 pairs
__device__ unsigned int g_wfQ[5760];       // dense1 weights k4..k5, bf16x2

__device__ __forceinline__ float frelu(float x) { return x > 0.f ? x : 0.f; }
__device__ __forceinline__ float dround(float x) {
    return x - sinf(x * TWO_PI_F) / TWO_PI_F;
}
__device__ __forceinline__ uint32_t pack_bf16x2(float lo, float hi) {
    uint32_t v; asm("cvt.rn.bf16x2.f32 %0, %1, %2;" : "=r"(v) : "f"(hi), "f"(lo)); return v;
}
__device__ __forceinline__ uint32_t smem_u32(const void* p) {
    uint32_t a;
    asm("{ .reg .u64 t; cvta.to.shared.u64 t, %1; cvt.u32.u64 %0, t; }" : "=r"(a) : "l"(p));
    return a;
}
__device__ __forceinline__ void cp_async16(uint32_t dst, const void* src) {
    asm volatile("cp.async.cg.shared.global [%0], [%1], 16;" :: "r"(dst), "l"(src));
}
#define CP_COMMIT() asm volatile("cp.async.commit_group;")
#define CP_WAIT(n)  asm volatile("cp.async.wait_group %0;" :: "n"(n))

// ---------------- kernel A1: fully parallel precompute ----------------
// b0..2: T; b3..19: Wc; b20..87: w2p (lane-innermost); b88..132: wf; b133..: slots
__global__ void __launch_bounds__(128) pre_a(
    const float* __restrict__ b1, const float* __restrict__ w2,
    const float* __restrict__ d1w, const int* __restrict__ rcv, int E)
{
    const int t = threadIdx.x;
    const int b = blockIdx.x;
    if (b < 3) {
        int item = b * 128 + t;
        if (item < 360) {
            int tap = item / 40, co = item - 40 * tap;
            float s = 0.f;
            #pragma unroll 8
            for (int ci = 0; ci < 40; ci++)
                s = fmaf(frelu(b1[ci]), __ldg(w2 + tap * 1600 + ci * 40 + co), s);
            g_T[item] = s;
        }
        return;
    }
    if (b < 20) {
        int idx = (b - 3) * 128 + t;
        if (idx < 2160) {
            int cls = idx / 240;
            int rem = idx - 240 * cls;
            int co = rem / 6, k = rem - 6 * co;
            int yc = cls / 3, xc = cls - 3 * yc;
            float s = 0.f;
            for (int p = 0; p < 256; ++p) {
                int y = p >> 4, x = p & 15;
                if (y >= 2 && y <= 13 && x >= 2 && x <= 13) continue;
                int pyc = (y == 0) ? 0 : (y == 15 ? 2 : 1);
                int pxc = (x == 0) ? 0 : (x == 15 ? 2 : 1);
                if (pyc == yc && pxc == xc)
                    s += __ldg(d1w + (p * 40 + co) * 6 + k);
            }
            g_Wc[idx] = s;
        }
        return;
    }
    if (b < 88) {
        int idx = (b - 20) * 128 + t;
        if (idx < 8640) {
            // idx = ((tap*3+s)*5 + nt)*64 + 2*lane + h ; lane = 4*g2 + tg
            int h = idx & 1;
            int l = (idx >> 1) & 31;
            int tg = l & 3, g2 = l >> 2;
            int nt = (idx >> 6) % 5;
            int s = (idx / 320) % 3;
            int tap = idx / 960;
            int co = 8 * nt + g2;
            int ci0 = 16 * s + 2 * tg + 8 * h;
            float lo = (ci0 < 40)     ? __ldg(w2 + tap * 1600 + ci0 * 40 + co)       : 0.f;
            float hi = (ci0 + 1 < 40) ? __ldg(w2 + tap * 1600 + (ci0 + 1) * 40 + co) : 0.f;
            g_w2p[idx] = pack_bf16x2(lo, hi);
        }
        return;
    }
    if (b < 133) {
        int idx = (b - 88) * 128 + t;
        if (idx < 5760) {
            int l = idx & 31, e = (idx >> 5) & 3, T = idx >> 7;
            int MT = T / 5, nt = T - 5 * MT;
            int g2v = l >> 2, tgv = l & 3;
            int p = 16 * MT + g2v + ((e >= 2) ? 8 : 0);
            int co = 8 * nt + 2 * tgv + (e & 1);
            int oy = 2 + p / 12, ox = 2 + p % 12;
            const float* wr = d1w + ((oy * 16 + ox) * 40 + co) * 6;
            g_wfP[idx] = make_uint2(pack_bf16x2(wr[0], wr[1]), pack_bf16x2(wr[2], wr[3]));
            g_wfQ[idx] = pack_bf16x2(wr[4], wr[5]);
        }
        return;
    }
    int e = (b - 133) * 128 + t;
    if (e < E) {
        int r = rcv[e];
        g_slot[r * 4 + ((e / 4032) & 3)] = e + 1;
    }
}

// ---------------- kernel A2: tiny dependent stage (c2, E, extk) ----------------
__global__ void __launch_bounds__(128) pre_b(const float* __restrict__ b2)
{
    const int t = threadIdx.x;
    __shared__ float E[360];
    __shared__ float P[8][6];
    if (t < 40) {
        float s = __ldg(b2 + t);
        #pragma unroll
        for (int tap = 0; tap < 9; tap++) s += g_T[tap * 40 + t];
        g_c2[t] = s;
    }
    for (int item = t; item < 360; item += 128) {
        int cls = item / 40, co = item - 40 * cls;
        int yc = cls / 3, xc = cls - 3 * yc;
        float s = __ldg(b2 + co);
        #pragma unroll
        for (int tap = 0; tap < 9; tap++) {
            int dy = tap / 3, dx = tap % 3;
            bool vy = !((yc == 0 && dy == 0) || (yc == 2 && dy == 2));
            bool vx = !((xc == 0 && dx == 0) || (xc == 2 && dx == 2));
            if (vy && vx) s += g_T[tap * 40 + co];
        }
        E[item] = frelu(s);
    }
    __syncthreads();
    if (t < 48) {
        int k = t % 6, c = t / 6;
        float acc = 0.f;
        #pragma unroll 5
        for (int m = 0; m < 45; ++m) {
            int item = c * 45 + m;
            acc = fmaf(E[item], g_Wc[item * 6 + k], acc);
        }
        P[c][k] = acc;
    }
    __syncthreads();
    if (t < 6) {
        float s = 0.f;
        #pragma unroll
        for (int c = 0; c < 8; c++) s += P[c][t];
        g_extk[t] = s;
    }
}

// ---------------- kernel 1: dual-patch, bf16 MMA, conflict-free B fragments ----------------
// smem words:
//   [0,8640)      w2p (lane-innermost fragment order)
//   [8656,16032)  D16 regions (guards + 2 x 3680, bases 8672 / 12352)
//   [16032,16728) tok (2 x 348)
//   [16728,17088) w1_s ; [17088,17128) b1_s ; [17128,17168) c2s ; [17168,17232) red_s
#define K1_SMEM_FLOATS 17232

#define MMA_TILE(Ap, CB, NTLO, NTHI) do {                                     \
    uint32_t a0 = __float_as_uint((Ap)[tg152]);                               \
    uint32_t a1 = __float_as_uint((Ap)[tg152 + 8]);                           \
    uint32_t a2 = __float_as_uint((Ap)[tg152 + 608]);                         \
    uint32_t a3 = __float_as_uint((Ap)[tg152 + 616]);                         \
    _Pragma("unroll")                                                         \
    for (int nt = (NTLO); nt < (NTHI); ++nt) {                                \
        float* c = C[(CB) + nt - (NTLO)];                                     \
        asm("mma.sync.aligned.m16n8k16.row.col.f32.bf16.bf16.f32 "            \
            "{%0,%1,%2,%3}, {%4,%5,%6,%7}, {%8,%9}, {%0,%1,%2,%3};"           \
            : "+f"(c[0]), "+f"(c[1]), "+f"(c[2]), "+f"(c[3])                  \
            : "r"(a0), "r"(a1), "r"(a2), "r"(a3), "r"(B0[nt]), "r"(B1[nt]));  \
    }                                                                         \
} while (0)

// B loads: lane-innermost layout -> one conflict-free LDS.64 per (s,nt)
#define KSTEPS(MT0, L0, H0, C0, MT1, L1, H1, C1, MT2, L2, H2, C2) do {        \
    _Pragma("unroll")                                                         \
    for (int s = 0; s < 3; ++s) {                                             \
        const float* wk = wb + s * 320 + 2 * l;                               \
        uint32_t B0[5], B1[5];                                                \
        _Pragma("unroll")                                                     \
        for (int nt = 0; nt < 5; ++nt) {                                      \
            unsigned long long wv = *(const unsigned long long*)(wk + 64 * nt); \
            B0[nt] = (uint32_t)wv; B1[nt] = (uint32_t)(wv >> 32);             \
        }                                                                     \
        const float* As = Db + s * 1216 + g2;                                 \
        MMA_TILE(As + 16 * (MT0), C0, L0, H0);                                \
        MMA_TILE(As + 16 * (MT1), C1, L1, H1);                                \
        MMA_TILE(As + 16 * (MT2), C2, L2, H2);                                \
    }                                                                         \
} while (0)

// bf16 dense weights: unpack via bit ops (exact), f32x2 accumulate
__device__ __forceinline__ void accW(unsigned long long* p3, float act, int idx) {
    unsigned long long a2;
    asm("mov.b64 %0, {%1, %2};" : "=l"(a2) : "f"(act), "f"(act));
    uint2 wp = __ldg(g_wfP + idx);
    uint32_t wq = __ldg(g_wfQ + idx);
    unsigned long long w64;
    asm("mov.b64 %0, {%1, %2};" : "=l"(w64) : "r"(wp.x << 16), "r"(wp.x & 0xffff0000u));
    asm("fma.rn.f32x2 %0, %1, %2, %0;" : "+l"(p3[0]) : "l"(a2), "l"(w64));
    asm("mov.b64 %0, {%1, %2};" : "=l"(w64) : "r"(wp.y << 16), "r"(wp.y & 0xffff0000u));
    asm("fma.rn.f32x2 %0, %1, %2, %0;" : "+l"(p3[1]) : "l"(a2), "l"(w64));
    asm("mov.b64 %0, {%1, %2};" : "=l"(w64) : "r"(wq << 16), "r"(wq & 0xffff0000u));
    asm("fma.rn.f32x2 %0, %1, %2, %0;" : "+l"(p3[2]) : "l"(a2), "l"(w64));
}

#define DEN_TILE(MT, NTLO, NTHI, CB) do {                                     \
    _Pragma("unroll")                                                         \
    for (int nt = (NTLO); nt < (NTHI); ++nt) {                                \
        float* c = C[(CB) + nt - (NTLO)];                                     \
        int co = 8 * nt + 2 * tg;                                             \
        int base = (((MT) * 5 + nt) * 4) * 32 + l;                            \
        accW(p3, frelu(c2s[co] + c[0]), base);                                \
        accW(p3, frelu(c2s[co + 1] + c[1]), base + 32);                       \
        accW(p3, frelu(c2s[co] + c[2]), base + 64);                           \
        accW(p3, frelu(c2s[co + 1] + c[3]), base + 96);                       \
    }                                                                         \
} while (0)

__global__ void __launch_bounds__(256, 3) patch_kernel(
    const float* __restrict__ img, const float* __restrict__ lab,
    const float* __restrict__ w1, const float* __restrict__ b1,
    const float* __restrict__ d1b)
{
    extern __shared__ float smem[];
    float* w2p   = smem;
    float* w1_s  = smem + 16728;
    float* b1_s  = smem + 17088;
    float* c2s   = smem + 17128;
    float* red_s = smem + 17168;

    const int t  = threadIdx.x;
    const int wg = t >> 7;
    const int wt = t & 127;
    float* tok_s = smem + 16032 + wg * 348;
    float* Dg    = smem + 8672 + wg * 3680;

    const int n = 2 * blockIdx.x + wg;
    const int g = n >> 10;
    const int ij = n & 1023;
    const int i = ij >> 5, j = ij & 31;
    const int sx = g & 1, sy = g >> 1;
    const int r0 = 16 * i + 8 * sx - 4;
    const int c0 = 16 * j + 8 * sy - 4;

    const uint32_t w2p_u = smem_u32(w2p);

    // stream ALL conv2 fragment weights (34.6KB) once
    #pragma unroll
    for (int r = 0; r < 9; ++r) {
        int k = t + 256 * r;
        if (k < 2160) cp_async16(w2p_u + k * 16, (const float4*)g_w2p + k);
    }
    CP_COMMIT();

    for (int k = t; k < 360; k += 256) w1_s[k] = w1[k];
    if (t < 40) { b1_s[t] = b1[t]; c2s[t] = g_c2[t]; }
    if (wt < 128) for (int k = wt; k < 324; k += 128) tok_s[k] = 0.f;
    // zero D + guards: floats [8656, 16032) = 7376 = 1844 float4
    {
        float4* z = (float4*)(smem + 8656);
        #pragma unroll
        for (int r = 0; r < 8; ++r) {
            int k = t + 256 * r;
            if (k < 1844) z[k] = make_float4(0.f, 0.f, 0.f, 0.f);
        }
    }
    __syncthreads();

    // tokens (central 8x8 only) + label sum
    float sum_lp = 0.f;
    if (wt < 64) {
        int py = 4 + (wt >> 3), px = 4 + (wt & 7);
        int gr = r0 + py, gc = c0 + px;
        tok_s[(py + 1) * 18 + px + 1] = __ldg(img + gr * 512 + gc);
        sum_lp = __ldg(lab + gr * 512 + gc);
    }
    #pragma unroll
    for (int o = 16; o; o >>= 1)
        sum_lp += __shfl_down_sync(0xffffffffu, sum_lp, o);
    if (wt < 64 && (wt & 31) == 0) red_s[wg * 2 + (wt >> 5)] = sum_lp;
    __syncthreads();
    if (wt == 0) {
        float sl = red_s[wg * 2] + red_s[wg * 2 + 1];
        g_label[n] = dround(dround(sl / 64.f));
    }

    // ---- conv1 delta -> bf16x2 channel-pair planes ----
    if (wt < 100) {
        int rr = 3 + wt / 10, cc = 3 + wt - 10 * (wt / 10);
        float t9[9];
        #pragma unroll
        for (int k = 0; k < 9; k++) t9[k] = tok_s[(rr + k / 3) * 18 + (cc + k % 3)];
        int dpos = (rr - 2) * 12 + (cc - 2);
        #pragma unroll 4
        for (int pr = 0; pr < 20; pr++) {
            float sA = 0.f, sB = 0.f;
            #pragma unroll
            for (int k = 0; k < 9; k++) {
                sA = fmaf(t9[k], w1_s[k * 40 + 2 * pr], sA);
                sB = fmaf(t9[k], w1_s[k * 40 + 2 * pr + 1], sB);
            }
            float bA = b1_s[2 * pr], bB = b1_s[2 * pr + 1];
            float dA = frelu(bA + sA) - frelu(bA);
            float dB = frelu(bB + sB) - frelu(bB);
            *(uint32_t*)(Dg + pr * 152 + dpos) = pack_bf16x2(dA, dB);
        }
    }

    CP_WAIT(0);
    __syncthreads();   // D16 + weights visible

    // ---- conv2 delta via bf16 mma: 9 taps straight through, no syncs ----
    const int w4 = (t >> 5) & 3, l = t & 31;
    const int g2 = l >> 2, tg = l & 3;
    const int tg152 = tg * 152;

    float C[12][4];
    #pragma unroll
    for (int a = 0; a < 12; a++)
        #pragma unroll
        for (int b = 0; b < 4; b++) C[a][b] = 0.f;

    if (w4 == 0) {
        for (int tap = 0; tap < 9; ++tap) {
            const float* wb = w2p + tap * 960;
            const float* Db = Dg + (tap / 3 - 1) * 12 + (tap % 3) - 1;
            KSTEPS(0, 0, 5, 0,   1, 0, 5, 5,   2, 0, 2, 10);
        }
    } else if (w4 == 1) {
        for (int tap = 0; tap < 9; ++tap) {
            const float* wb = w2p + tap * 960;
            const float* Db = Dg + (tap / 3 - 1) * 12 + (tap % 3) - 1;
            KSTEPS(2, 2, 5, 0,   3, 0, 5, 3,   4, 0, 3, 8);
        }
    } else if (w4 == 2) {
        for (int tap = 0; tap < 9; ++tap) {
            const float* wb = w2p + tap * 960;
            const float* Db = Dg + (tap / 3 - 1) * 12 + (tap % 3) - 1;
            KSTEPS(4, 3, 5, 0,   5, 0, 5, 2,   6, 0, 4, 7);
        }
    } else {
        for (int tap = 0; tap < 9; ++tap) {
            const float* wb = w2p + tap * 960;
            const float* Db = Dg + (tap / 3 - 1) * 12 + (tap % 3) - 1;
            KSTEPS(6, 4, 5, 0,   7, 0, 5, 1,   8, 0, 5, 6);
        }
    }

    // ---- dense1 straight from accumulators (bf16 weights) ----
    unsigned long long p3[3] = {0ull, 0ull, 0ull};
    if (w4 == 0) {
        DEN_TILE(0, 0, 5, 0); DEN_TILE(1, 0, 5, 5); DEN_TILE(2, 0, 2, 10);
    } else if (w4 == 1) {
        DEN_TILE(2, 2, 5, 0); DEN_TILE(3, 0, 5, 3); DEN_TILE(4, 0, 3, 8);
    } else if (w4 == 2) {
        DEN_TILE(4, 3, 5, 0); DEN_TILE(5, 0, 5, 2); DEN_TILE(6, 0, 4, 7);
    } else {
        DEN_TILE(6, 4, 5, 0); DEN_TILE(7, 0, 5, 1); DEN_TILE(8, 0, 5, 6);
    }
    float part[6];
    #pragma unroll
    for (int k2 = 0; k2 < 3; k2++)
        asm("mov.b64 {%0, %1}, %2;" : "=f"(part[2 * k2]), "=f"(part[2 * k2 + 1]) : "l"(p3[k2]));
    #pragma unroll
    for (int k = 0; k < 6; k++)
        #pragma unroll
        for (int o = 16; o; o >>= 1) part[k] += __shfl_down_sync(0xffffffffu, part[k], o);
    __syncthreads();
    if (l == 0) {
        #pragma unroll
        for (int k = 0; k < 6; k++) red_s[8 + wg * 24 + w4 * 6 + k] = part[k];
    }
    __syncthreads();
    if (wt < 8) {
        float val = 0.f;
        if (wt < 6) {
            const float* rb = red_s + 8 + wg * 24;
            float s = rb[wt] + rb[6 + wt] + rb[12 + wt] + rb[18 + wt];
            val = frelu(s + g_extk[wt] + d1b[wt]);
        }
        g_nodes[n * 8 + wt] = val;
    }
}

// ---------------- kernel 2: fused edge MLP + agg + node MLP + CE ----------------
__global__ void __launch_bounds__(128) graph_kernel(
    const int* __restrict__ snd,
    const float* __restrict__ we0, const float* __restrict__ be0,
    const float* __restrict__ we1, const float* __restrict__ be1,
    const float* __restrict__ we2, const float* __restrict__ be2,
    const float* __restrict__ we3, const float* __restrict__ be3,
    const float* __restrict__ wn0, const float* __restrict__ bn0,
    const float* __restrict__ wn1, const float* __restrict__ bn1,
    const float* __restrict__ wn2, const float* __restrict__ bn2,
    const float* __restrict__ wn3, const float* __restrict__ bn3,
    const float* __restrict__ wout, const float* __restrict__ bout,
    float* __restrict__ out)
{
    __shared__ float sw[422];
    int t = threadIdx.x;
    {
        const float* srcs[18] = {we0, be0, we1, be1, we2, be2, we3, be3,
                                 wn0, bn0, wn1, bn1, wn2, bn2, wn3, bn3, wout, bout};
        const int sizes[18] = {65, 5, 25, 5, 25, 5, 50, 10, 85, 5, 25, 5, 25, 5, 50, 10, 20, 2};
        int off = 0;
        #pragma unroll
        for (int a = 0; a < 18; a++) {
            for (int k = t; k < sizes[a]; k += 128) sw[off + k] = __ldg(srcs[a] + k);
            off += sizes[a];
        }
    }
    __syncthreads();
    const float* s_we0 = sw;        const float* s_be0 = sw + 65;
    const float* s_we1 = sw + 70;   const float* s_be1 = sw + 95;
    const float* s_we2 = sw + 100;  const float* s_be2 = sw + 125;
    const float* s_we3 = sw + 130;  const float* s_be3 = sw + 180;
    const float* s_wn0 = sw + 190;  const float* s_bn0 = sw + 275;
    const float* s_wn1 = sw + 280;  const float* s_bn1 = sw + 305;
    const float* s_wn2 = sw + 310;  const float* s_bn2 = sw + 335;
    const float* s_wn3 = sw + 340;  const float* s_bn3 = sw + 390;
    const float* s_wout = sw + 400; const float* s_bout = sw + 420;

    int n = blockIdx.x * 32 + (t >> 2);
    int q = t & 3;

    int sv = g_slot[n * 4 + q];
    g_slot[n * 4 + q] = 0;                 // reset for next launch (deterministic)

    float4 r0v = *(const float4*)(g_nodes + n * 8);
    float2 r1v = *(const float2*)(g_nodes + n * 8 + 4);

    float ef[10];
    #pragma unroll
    for (int k = 0; k < 10; k++) ef[k] = 0.f;

    if (sv) {
        int e = sv - 1;
        int s = snd[e];
        float4 s0v = *(const float4*)(g_nodes + s * 8);
        float2 s1v = *(const float2*)(g_nodes + s * 8 + 4);
        float x[13];
        x[0] = s0v.x; x[1] = s0v.y; x[2] = s0v.z; x[3] = s0v.w; x[4] = s1v.x; x[5] = s1v.y;
        x[6] = r0v.x; x[7] = r0v.y; x[8] = r0v.z; x[9] = r0v.w; x[10] = r1v.x; x[11] = r1v.y;
        x[12] = 1.f;

        float h0[5], h1[5], h2[5];
        #pragma unroll
        for (int k = 0; k < 5; k++) {
            float a = s_be0[k];
            #pragma unroll
            for (int i2 = 0; i2 < 13; i2++) a = fmaf(x[i2], s_we0[i2 * 5 + k], a);
            h0[k] = frelu(a);
        }
        #pragma unroll
        for (int k = 0; k < 5; k++) {
            float a = s_be1[k];
            #pragma unroll
            for (int i2 = 0; i2 < 5; i2++) a = fmaf(h0[i2], s_we1[i2 * 5 + k], a);
            h1[k] = frelu(a);
        }
        #pragma unroll
        for (int k = 0; k < 5; k++) {
            float a = s_be2[k];
            #pragma unroll
            for (int i2 = 0; i2 < 5; i2++) a = fmaf(h1[i2], s_we2[i2 * 5 + k], a);
            h2[k] = frelu(a);
        }
        #pragma unroll
        for (int k = 0; k < 10; k++) {
            float a = s_be3[k];
            #pragma unroll
            for (int i2 = 0; i2 < 5; i2++) a = fmaf(h2[i2], s_we3[i2 * 10 + k], a);
            ef[k] = a;
        }
    }
    #pragma unroll
    for (int k = 0; k < 10; k++) {
        ef[k] += __shfl_xor_sync(0xffffffffu, ef[k], 1);
        ef[k] += __shfl_xor_sync(0xffffffffu, ef[k], 2);
    }
    if (q != 0) return;

    float x[17];
    x[0] = r0v.x; x[1] = r0v.y; x[2] = r0v.z; x[3] = r0v.w; x[4] = r1v.x; x[5] = r1v.y;
    #pragma unroll
    for (int k = 0; k < 10; k++) x[6 + k] = ef[k];
    x[16] = 1.f;

    float h0[5], h1[5], h2[5], o[10];
    #pragma unroll
    for (int k = 0; k < 5; k++) {
        float a = s_bn0[k];
        #pragma unroll
        for (int i2 = 0; i2 < 17; i2++) a = fmaf(x[i2], s_wn0[i2 * 5 + k], a);
        h0[k] = frelu(a);
    }
    #pragma unroll
    for (int k = 0; k < 5; k++) {
        float a = s_bn1[k];
        #pragma unroll
        for (int i2 = 0; i2 < 5; i2++) a = fmaf(h0[i2], s_wn1[i2 * 5 + k], a);
        h1[k] = frelu(a);
    }
    #pragma unroll
    for (int k = 0; k < 5; k++) {
        float a = s_bn2[k];
        #pragma unroll
        for (int i2 = 0; i2 < 5; i2++) a = fmaf(h1[i2], s_wn2[i2 * 5 + k], a);
        h2[k] = frelu(a);
    }
    #pragma unroll
    for (int k = 0; k < 10; k++) {
        float a = s_bn3[k];
        #pragma unroll
        for (int i2 = 0; i2 < 5; i2++) a = fmaf(h2[i2], s_wn3[i2 * 10 + k], a);
        o[k] = a;
    }
    float l0 = s_bout[0], l1 = s_bout[1];
    #pragma unroll
    for (int i2 = 0; i2 < 10; i2++) {
        l0 = fmaf(o[i2], s_wout[i2 * 2 + 0], l0);
        l1 = fmaf(o[i2], s_wout[i2 * 2 + 1], l1);
    }
    float m = fmaxf(l0, l1);
    float lse = m + logf(expf(l0 - m) + expf(l1 - m));
    float sv2 = g_label[n];
    out[n] = -((1.f - sv2) * (l0 - lse) + sv2 * (l1 - lse));
}

// ---------------- launch ----------------
extern "C" void kernel_launch(void* const* d_in, const int* in_sizes, int n_in,
                              void* d_out, int out_size)
{
    const float* img = (const float*)d_in[0];
    const float* lab = (const float*)d_in[1];
    const float* w1  = (const float*)d_in[3];
    const float* b1  = (const float*)d_in[4];
    const float* w2  = (const float*)d_in[5];
    const float* b2  = (const float*)d_in[6];
    const float* d1w = (const float*)d_in[7];
    const float* d1b = (const float*)d_in[8];
    const float* we0 = (const float*)d_in[9];
    const float* be0 = (const float*)d_in[10];
    const float* we1 = (const float*)d_in[11];
    const float* be1 = (const float*)d_in[12];
    const float* we2 = (const float*)d_in[13];
    const float* be2 = (const float*)d_in[14];
    const float* we3 = (const float*)d_in[15];
    const float* be3 = (const float*)d_in[16];
    const float* wn0 = (const float*)d_in[17];
    const float* bn0 = (const float*)d_in[18];
    const float* wn1 = (const float*)d_in[19];
    const float* bn1 = (const float*)d_in[20];
    const float* wn2 = (const float*)d_in[21];
    const float* bn2 = (const float*)d_in[22];
    const float* wn3 = (const float*)d_in[23];
    const float* bn3 = (const float*)d_in[24];
    const float* wout = (const float*)d_in[25];
    const float* bout = (const float*)d_in[26];
    const int* snd = (const int*)d_in[27];
    const int* rcv = (const int*)d_in[28];
    int E = in_sizes[27];

    int smem_bytes = K1_SMEM_FLOATS * (int)sizeof(float);
    static int configured = -1;
    if (configured != smem_bytes) {
        cudaFuncSetAttribute(patch_kernel, cudaFuncAttributeMaxDynamicSharedMemorySize, smem_bytes);
        configured = smem_bytes;
    }

    int nblk = 133 + (E + 127) / 128;
    pre_a<<<nblk, 128>>>(b1, w2, d1w, rcv, E);
    pre_b<<<1, 128>>>(b2);
    patch_kernel<<<2048, 256, smem_bytes>>>(img, lab, w1, b1, d1b);
    graph_kernel<<<128, 128>>>(snd, we0, be0, we1, be1, we2, be2, we3, be3,
                               wn0, bn0, wn1, bn1, wn2, bn2, wn3, bn3,
                               wout, bout, (float*)d_out);

    (void)n_in; (void)out_size;
}